// round 1
// baseline (speedup 1.0000x reference)
#include <cuda_runtime.h>

// Problem constants
#define BB 2
#define NN 2048
#define EE 768
#define HH 12
#define DD 64
#define E3 (3*EE)
#define MM (BB*NN)   // 4096 rows

// ---------------- scratch (device globals; no allocations allowed) ---------
__device__ float g_xn[MM*EE];          // layernormed input
__device__ float g_q[BB*HH*NN*DD];     // [b][h][n][d]
__device__ float g_k[BB*HH*NN*DD];
__device__ float g_v[BB*HH*NN*DD];
__device__ float g_att[MM*EE];         // attention output, [b][n][e]

// ---------------- LayerNorm: one block per row (768 elems, 256 threads) ----
__global__ __launch_bounds__(256) void ln_kernel(const float* __restrict__ x,
                                                 const float* __restrict__ g,
                                                 const float* __restrict__ bta) {
    int row = blockIdx.x;
    const float* xr = x + row * EE;
    int t = threadIdx.x;
    float v0 = xr[t], v1 = xr[t + 256], v2 = xr[t + 512];
    float s  = v0 + v1 + v2;
    float sq = v0*v0 + v1*v1 + v2*v2;
    __shared__ float rs[8], rq[8];
    #pragma unroll
    for (int o = 16; o; o >>= 1) {
        s  += __shfl_xor_sync(0xffffffffu, s,  o);
        sq += __shfl_xor_sync(0xffffffffu, sq, o);
    }
    if ((t & 31) == 0) { rs[t >> 5] = s; rq[t >> 5] = sq; }
    __syncthreads();
    float S = 0.f, Q = 0.f;
    #pragma unroll
    for (int i = 0; i < 8; i++) { S += rs[i]; Q += rq[i]; }
    float mu  = S * (1.0f / EE);
    float var = Q * (1.0f / EE) - mu * mu;
    float inv = rsqrtf(var + 1e-5f);
    float* o = g_xn + row * EE;
    o[t]       = (v0 - mu) * inv * g[t]       + bta[t];
    o[t + 256] = (v1 - mu) * inv * g[t + 256] + bta[t + 256];
    o[t + 512] = (v2 - mu) * inv * g[t + 512] + bta[t + 512];
}

// ---------------- QKV GEMM: C[4096,2304] = xn @ Wqkv^T + b, scatter q/k/v ---
// 64x64 tile, BK=16, 256 threads, 4x4 micro-tile. Smem stored k-major
// (transposed) so the inner loop is 2x LDS.128 + 16 FFMA.
__global__ __launch_bounds__(256) void qkv_gemm(const float* __restrict__ W,
                                                const float* __restrict__ bias) {
    __shared__ float As[16][68];   // [k][m]
    __shared__ float Bs[16][68];   // [k][n]
    int m0 = blockIdx.y * 64, n0 = blockIdx.x * 64;
    int tid = threadIdx.x, ty = tid >> 4, tx = tid & 15;
    int lr = tid >> 2, lc = (tid & 3) * 4;
    float acc[4][4] = {};
    for (int k0 = 0; k0 < EE; k0 += 16) {
        float4 a4 = *(const float4*)(g_xn + (m0 + lr) * EE + k0 + lc);
        float4 b4 = *(const float4*)(W    + (n0 + lr) * EE + k0 + lc);
        As[lc+0][lr] = a4.x; As[lc+1][lr] = a4.y; As[lc+2][lr] = a4.z; As[lc+3][lr] = a4.w;
        Bs[lc+0][lr] = b4.x; Bs[lc+1][lr] = b4.y; Bs[lc+2][lr] = b4.z; Bs[lc+3][lr] = b4.w;
        __syncthreads();
        #pragma unroll
        for (int kk = 0; kk < 16; kk++) {
            float4 av = *(const float4*)&As[kk][ty * 4];
            float4 bv = *(const float4*)&Bs[kk][tx * 4];
            float a[4] = {av.x, av.y, av.z, av.w};
            float b[4] = {bv.x, bv.y, bv.z, bv.w};
            #pragma unroll
            for (int i = 0; i < 4; i++)
                #pragma unroll
                for (int j = 0; j < 4; j++)
                    acc[i][j] += a[i] * b[j];
        }
        __syncthreads();
    }
    // scatter: j = h*192 + dd*3 + s   (reshape (h, d, 3), qkv innermost)
    #pragma unroll
    for (int i = 0; i < 4; i++) {
        int gi = m0 + ty * 4 + i;
        int bI = gi >> 11;             // / NN
        int nI = gi & (NN - 1);
        #pragma unroll
        for (int j = 0; j < 4; j++) {
            int gj = n0 + tx * 4 + j;
            float val = acc[i][j] + bias[gj];
            int t3 = gj / 3;
            int s  = gj - t3 * 3;
            int dd = t3 & 63;
            int hh = gj / 192;
            int idx = ((bI * HH + hh) * NN + nI) * DD + dd;
            if (s == 0)      g_q[idx] = val;
            else if (s == 1) g_k[idx] = val;
            else             g_v[idx] = val;
        }
    }
}

// ---------------- Flash attention (fp32, 64q x 64k tiles) ------------------
#define ATTN_SMEM ((2*64*68 + 64*64 + 64*65) * 4)

__global__ __launch_bounds__(256) void attn_kernel() {
    extern __shared__ float sm[];
    float* Qt = sm;               // [d=64][row 68]  (k-major, *8 folded in)
    float* Kt = Qt + 64 * 68;     // [d=64][col 68]
    float* Vs = Kt + 64 * 68;     // [key=64][d=64]
    float* Ps = Vs + 64 * 64;     // [row=64][65]
    int b = blockIdx.z, h = blockIdx.y;
    int q0 = blockIdx.x * 64;
    int tid = threadIdx.x, ty = tid >> 4, tx = tid & 15;
    const float* qb = g_q + ((b * HH + h) * NN) * DD;
    const float* kb = g_k + ((b * HH + h) * NN) * DD;
    const float* vb = g_v + ((b * HH + h) * NN) * DD;

    #pragma unroll
    for (int i0 = 0; i0 < 16; i0++) {
        int idx = i0 * 256 + tid;
        int r = idx >> 6, c = idx & 63;
        Qt[c * 68 + r] = qb[(q0 + r) * DD + c] * 8.0f;   // scores = qk * sqrt(d)
    }
    float o[4][4] = {};
    float mrow[4], lrow[4];
    #pragma unroll
    for (int i = 0; i < 4; i++) { mrow[i] = -1e30f; lrow[i] = 0.f; }
    __syncthreads();

    for (int kt = 0; kt < NN / 64; kt++) {
        #pragma unroll
        for (int i0 = 0; i0 < 16; i0++) {
            int idx = i0 * 256 + tid;
            int r = idx >> 6, c = idx & 63;
            Kt[c * 68 + r] = kb[(kt * 64 + r) * DD + c];
            Vs[r * 64 + c] = vb[(kt * 64 + r) * DD + c];
        }
        __syncthreads();

        // S = Q K^T  (per-thread 4x4)
        float s[4][4] = {};
        #pragma unroll 8
        for (int kk = 0; kk < 64; kk++) {
            float4 qa = *(const float4*)&Qt[kk * 68 + ty * 4];
            float4 ka = *(const float4*)&Kt[kk * 68 + tx * 4];
            float q_[4] = {qa.x, qa.y, qa.z, qa.w};
            float k_[4] = {ka.x, ka.y, ka.z, ka.w};
            #pragma unroll
            for (int i = 0; i < 4; i++)
                #pragma unroll
                for (int j = 0; j < 4; j++)
                    s[i][j] += q_[i] * k_[j];
        }

        // online softmax (row stats replicated across the 16 tx lanes)
        #pragma unroll
        for (int i = 0; i < 4; i++) {
            float mx = fmaxf(fmaxf(s[i][0], s[i][1]), fmaxf(s[i][2], s[i][3]));
            mx = fmaxf(mx, __shfl_xor_sync(0xffffffffu, mx, 8));
            mx = fmaxf(mx, __shfl_xor_sync(0xffffffffu, mx, 4));
            mx = fmaxf(mx, __shfl_xor_sync(0xffffffffu, mx, 2));
            mx = fmaxf(mx, __shfl_xor_sync(0xffffffffu, mx, 1));
            float mnew  = fmaxf(mrow[i], mx);
            float alpha = __expf(mrow[i] - mnew);
            float sum = 0.f;
            #pragma unroll
            for (int j = 0; j < 4; j++) {
                float p = __expf(s[i][j] - mnew);
                sum += p;
                Ps[(ty * 4 + i) * 65 + tx * 4 + j] = p;
            }
            sum += __shfl_xor_sync(0xffffffffu, sum, 8);
            sum += __shfl_xor_sync(0xffffffffu, sum, 4);
            sum += __shfl_xor_sync(0xffffffffu, sum, 2);
            sum += __shfl_xor_sync(0xffffffffu, sum, 1);
            lrow[i] = lrow[i] * alpha + sum;
            mrow[i] = mnew;
            #pragma unroll
            for (int j = 0; j < 4; j++) o[i][j] *= alpha;
        }
        __syncthreads();

        // O += P V
        #pragma unroll 8
        for (int kk = 0; kk < 64; kk++) {
            float4 vv = *(const float4*)&Vs[kk * 64 + tx * 4];
            float v_[4] = {vv.x, vv.y, vv.z, vv.w};
            float p_[4];
            #pragma unroll
            for (int i = 0; i < 4; i++) p_[i] = Ps[(ty * 4 + i) * 65 + kk];
            #pragma unroll
            for (int i = 0; i < 4; i++)
                #pragma unroll
                for (int j = 0; j < 4; j++)
                    o[i][j] += p_[i] * v_[j];
        }
        __syncthreads();
    }

    #pragma unroll
    for (int i = 0; i < 4; i++) {
        float inv = 1.0f / lrow[i];
        int n = q0 + ty * 4 + i;
        #pragma unroll
        for (int j = 0; j < 4; j++)
            g_att[(b * NN + n) * EE + h * DD + tx * 4 + j] = o[i][j] * inv;
    }
}

// ---------------- Proj GEMM + bias + residual -------------------------------
__global__ __launch_bounds__(256) void proj_gemm(const float* __restrict__ x,
                                                 const float* __restrict__ W,
                                                 const float* __restrict__ bias,
                                                 float* __restrict__ out) {
    __shared__ float As[16][68];
    __shared__ float Bs[16][68];
    int m0 = blockIdx.y * 64, n0 = blockIdx.x * 64;
    int tid = threadIdx.x, ty = tid >> 4, tx = tid & 15;
    int lr = tid >> 2, lc = (tid & 3) * 4;
    float acc[4][4] = {};
    for (int k0 = 0; k0 < EE; k0 += 16) {
        float4 a4 = *(const float4*)(g_att + (m0 + lr) * EE + k0 + lc);
        float4 b4 = *(const float4*)(W     + (n0 + lr) * EE + k0 + lc);
        As[lc+0][lr] = a4.x; As[lc+1][lr] = a4.y; As[lc+2][lr] = a4.z; As[lc+3][lr] = a4.w;
        Bs[lc+0][lr] = b4.x; Bs[lc+1][lr] = b4.y; Bs[lc+2][lr] = b4.z; Bs[lc+3][lr] = b4.w;
        __syncthreads();
        #pragma unroll
        for (int kk = 0; kk < 16; kk++) {
            float4 av = *(const float4*)&As[kk][ty * 4];
            float4 bv = *(const float4*)&Bs[kk][tx * 4];
            float a[4] = {av.x, av.y, av.z, av.w};
            float b[4] = {bv.x, bv.y, bv.z, bv.w};
            #pragma unroll
            for (int i = 0; i < 4; i++)
                #pragma unroll
                for (int j = 0; j < 4; j++)
                    acc[i][j] += a[i] * b[j];
        }
        __syncthreads();
    }
    #pragma unroll
    for (int i = 0; i < 4; i++) {
        int gi = m0 + ty * 4 + i;
        #pragma unroll
        for (int j = 0; j < 4; j++) {
            int gj = n0 + tx * 4 + j;
            out[gi * EE + gj] = x[gi * EE + gj] + acc[i][j] + bias[gj];
        }
    }
}

// ---------------- launch -----------------------------------------------------
extern "C" void kernel_launch(void* const* d_in, const int* in_sizes, int n_in,
                              void* d_out, int out_size) {
    const float* in[14];
    for (int i = 0; i < 14; i++) in[i] = (const float*)d_in[i];
    float* out = (float*)d_out;

    cudaFuncSetAttribute(attn_kernel,
                         cudaFuncAttributeMaxDynamicSharedMemorySize, ATTN_SMEM);

    for (int m = 0; m < 2; m++) {
        const float* x    = in[m];
        const float* ln_g = in[2 + 6 * m];
        const float* ln_b = in[3 + 6 * m];
        const float* wq   = in[4 + 6 * m];
        const float* bq   = in[5 + 6 * m];
        const float* wp   = in[6 + 6 * m];
        const float* bp   = in[7 + 6 * m];

        ln_kernel<<<MM, 256>>>(x, ln_g, ln_b);
        qkv_gemm<<<dim3(E3 / 64, MM / 64), 256>>>(wq, bq);
        attn_kernel<<<dim3(NN / 64, HH, BB), 256, ATTN_SMEM>>>();
        proj_gemm<<<dim3(EE / 64, MM / 64), 256>>>(x, wp, bp,
                                                   out + (size_t)m * MM * EE);
    }
}

// round 6
// speedup vs baseline: 1.6070x; 1.6070x over previous
#include <cuda_runtime.h>
#include <cuda_bf16.h>
#include <cstdint>

// Problem constants
#define BB 2
#define NN 2048
#define EE 768
#define HH 12
#define DD 64
#define E3 (3*EE)
#define MM (BB*NN)   // 4096 rows

// ------------------------------ helpers ------------------------------------
__device__ __forceinline__ uint32_t smem_u32(const void* p) {
    uint32_t a;
    asm("{ .reg .u64 t; cvta.to.shared.u64 t, %1; cvt.u32.u64 %0, t; }"
        : "=r"(a) : "l"(p));
    return a;
}

__device__ __forceinline__ void ldsm4(uint32_t* r, uint32_t addr) {
    asm volatile("ldmatrix.sync.aligned.m8n8.x4.shared.b16 {%0,%1,%2,%3}, [%4];"
        : "=r"(r[0]), "=r"(r[1]), "=r"(r[2]), "=r"(r[3]) : "r"(addr));
}

__device__ __forceinline__ void mma16816(float* c, const uint32_t* a, const uint32_t* b) {
    asm volatile("mma.sync.aligned.m16n8k16.row.col.f32.bf16.bf16.f32 "
        "{%0,%1,%2,%3}, {%4,%5,%6,%7}, {%8,%9}, {%0,%1,%2,%3};"
        : "+f"(c[0]), "+f"(c[1]), "+f"(c[2]), "+f"(c[3])
        : "r"(a[0]), "r"(a[1]), "r"(a[2]), "r"(a[3]), "r"(b[0]), "r"(b[1]));
}

// FFMA-only exp for x <= 0 (avoids the MUFU throughput wall). ~2e-6 rel err.
__device__ __forceinline__ float fexp(float x) {
    float t = fmaxf(x * 1.4426950408889634f, -126.0f);
    float z = t + 12582912.0f;                     // round-to-nearest-int trick
    int   i = __float_as_int(z) - 0x4B400000;      // integer part n
    float f = t - (z - 12582912.0f);               // frac in [-0.5, 0.5]
    float r = 0.0013333558f;
    r = r * f + 0.009618129f;
    r = r * f + 0.05550411f;
    r = r * f + 0.24022652f;
    r = r * f + 0.6931472f;
    r = r * f + 1.0f;                              // 2^f
    return __int_as_float(__float_as_int(r) + (i << 23));
}

__device__ __forceinline__ void split_st(__nv_bfloat16* hi, __nv_bfloat16* lo,
                                         size_t idx, float v) {
    __nv_bfloat16 h = __float2bfloat16(v);
    hi[idx] = h;
    lo[idx] = __float2bfloat16(v - __bfloat162float(h));
}

// ---------------- scratch (device globals; no allocations) -----------------
// NOTE: these must ONLY be referenced inside device code. Passing them as
// kernel arguments from host code silently passes a host shadow address
// (that was the R3-R5 bug: A operand read as zeros -> out == x).
__device__ __align__(256) __nv_bfloat16 g_xn_hi[MM*EE],  g_xn_lo[MM*EE];
__device__ __align__(256) __nv_bfloat16 g_att_hi[MM*EE], g_att_lo[MM*EE];
__device__ __align__(256) __nv_bfloat16 g_w_hi[E3*EE],   g_w_lo[E3*EE];
__device__ __align__(256) __nv_bfloat16 g_qhi[BB*HH*NN*DD], g_qlo[BB*HH*NN*DD];
__device__ __align__(256) __nv_bfloat16 g_khi[BB*HH*NN*DD], g_klo[BB*HH*NN*DD];
__device__ __align__(256) __nv_bfloat16 g_vhi[BB*HH*NN*DD], g_vlo[BB*HH*NN*DD];

// ---------------- LayerNorm + hi/lo split ----------------------------------
__global__ __launch_bounds__(256) void ln_kernel(const float* __restrict__ x,
                                                 const float* __restrict__ g,
                                                 const float* __restrict__ bta) {
    int row = blockIdx.x;
    const float* xr = x + (size_t)row * EE;
    int t = threadIdx.x;
    float v0 = xr[t], v1 = xr[t + 256], v2 = xr[t + 512];
    float s  = v0 + v1 + v2;
    float sq = v0*v0 + v1*v1 + v2*v2;
    __shared__ float rs[8], rq[8];
    #pragma unroll
    for (int o = 16; o; o >>= 1) {
        s  += __shfl_xor_sync(0xffffffffu, s,  o);
        sq += __shfl_xor_sync(0xffffffffu, sq, o);
    }
    if ((t & 31) == 0) { rs[t >> 5] = s; rq[t >> 5] = sq; }
    __syncthreads();
    float S = 0.f, Q = 0.f;
    #pragma unroll
    for (int i = 0; i < 8; i++) { S += rs[i]; Q += rq[i]; }
    float mu  = S * (1.0f / EE);
    float var = Q * (1.0f / EE) - mu * mu;
    float inv = rsqrtf(var + 1e-5f);
    #pragma unroll
    for (int p = 0; p < 3; p++) {
        int c = t + p * 256;
        float v = (p == 0 ? v0 : p == 1 ? v1 : v2);
        float y = (v - mu) * inv * g[c] + bta[c];
        split_st(g_xn_hi, g_xn_lo, (size_t)row * EE + c, y);
    }
}

// ---------------- weight split ----------------------------------------------
__global__ __launch_bounds__(256) void split_kernel(const float* __restrict__ src, int n) {
    int i = blockIdx.x * 256 + threadIdx.x;
    if (i < n) split_st(g_w_hi, g_w_lo, i, src[i]);
}

// ---------------- split-bf16 GEMM via mma.sync ------------------------------
// C[128,128] tile of A[M,768] @ B[N,768]^T. 8 warps (4m x 2n), warp 32x64.
// A selected INSIDE the kernel by mode (device globals are not valid host args):
// mode 0: A = g_xn (QKV: bias + scatter to q/k/v hi-lo planes; q pre-scaled by 8)
// mode 1: A = g_att (proj: bias + residual, fp32 out)
#define GLD 72
#define GEMM_SMEM (4 * 128 * GLD * 2)   // 73728 B

__global__ __launch_bounds__(256, 2) void gemm_mma(
        const float* __restrict__ bias,
        const float* __restrict__ resid, float* __restrict__ outp, int mode) {
    extern __shared__ char smraw[];
    __nv_bfloat16* sAh = (__nv_bfloat16*)smraw;
    __nv_bfloat16* sAl = sAh + 128 * GLD;
    __nv_bfloat16* sBh = sAl + 128 * GLD;
    __nv_bfloat16* sBl = sBh + 128 * GLD;
    uint32_t sb = smem_u32(smraw);
    const uint32_t PLANE = 128 * GLD * 2;   // bytes per plane

    const __nv_bfloat16* __restrict__ Ahi = (mode == 0) ? g_xn_hi : g_att_hi;
    const __nv_bfloat16* __restrict__ Alo = (mode == 0) ? g_xn_lo : g_att_lo;

    int tid = threadIdx.x;
    int wid = tid >> 5, lane = tid & 31;
    int wm = wid >> 1, wn = wid & 1;
    int m0 = blockIdx.y * 128, n0 = blockIdx.x * 128;

    float acc[2][8][4];
    #pragma unroll
    for (int a = 0; a < 2; a++)
        #pragma unroll
        for (int b = 0; b < 8; b++)
            #pragma unroll
            for (int c = 0; c < 4; c++) acc[a][b][c] = 0.f;

    for (int k0 = 0; k0 < EE; k0 += 64) {
        __syncthreads();
        #pragma unroll
        for (int i = 0; i < 4; i++) {
            int idx = i * 256 + tid;            // 0..1023
            int r = idx >> 3, c8 = (idx & 7) * 8;
            *(uint4*)(sAh + r * GLD + c8) =
                *(const uint4*)(Ahi + (size_t)(m0 + r) * EE + k0 + c8);
            *(uint4*)(sAl + r * GLD + c8) =
                *(const uint4*)(Alo + (size_t)(m0 + r) * EE + k0 + c8);
            *(uint4*)(sBh + r * GLD + c8) =
                *(const uint4*)(g_w_hi + (size_t)(n0 + r) * EE + k0 + c8);
            *(uint4*)(sBl + r * GLD + c8) =
                *(const uint4*)(g_w_lo + (size_t)(n0 + r) * EE + k0 + c8);
        }
        __syncthreads();
        #pragma unroll
        for (int ks = 0; ks < 4; ks++) {
            uint32_t ah[2][4], al[2][4];
            #pragma unroll
            for (int mt = 0; mt < 2; mt++) {
                uint32_t ad = sb +
                    ((wm * 32 + mt * 16 + (lane & 15)) * GLD + ks * 16 + ((lane >> 4) * 8)) * 2;
                ldsm4(ah[mt], ad);
                ldsm4(al[mt], ad + PLANE);
            }
            #pragma unroll
            for (int g = 0; g < 4; g++) {
                uint32_t r4h[4], r4l[4];
                uint32_t bd = sb + 2 * PLANE +
                    ((wn * 64 + g * 16 + (lane & 15)) * GLD + ks * 16 + ((lane >> 4) * 8)) * 2;
                ldsm4(r4h, bd);
                ldsm4(r4l, bd + PLANE);
                uint32_t bh0[2] = {r4h[0], r4h[2]}, bh1[2] = {r4h[1], r4h[3]};
                uint32_t bl0[2] = {r4l[0], r4l[2]}, bl1[2] = {r4l[1], r4l[3]};
                #pragma unroll
                for (int mt = 0; mt < 2; mt++) {
                    mma16816(acc[mt][g*2],   ah[mt], bh0);
                    mma16816(acc[mt][g*2],   ah[mt], bl0);
                    mma16816(acc[mt][g*2],   al[mt], bh0);
                    mma16816(acc[mt][g*2+1], ah[mt], bh1);
                    mma16816(acc[mt][g*2+1], ah[mt], bl1);
                    mma16816(acc[mt][g*2+1], al[mt], bh1);
                }
            }
        }
    }

    // epilogue
    #pragma unroll
    for (int mt = 0; mt < 2; mt++) {
        int r0 = m0 + wm * 32 + mt * 16 + (lane >> 2);
        #pragma unroll
        for (int j = 0; j < 8; j++) {
            int c0 = n0 + wn * 64 + j * 8 + (lane & 3) * 2;
            #pragma unroll
            for (int e = 0; e < 4; e++) {
                int gr = r0 + (e >> 1) * 8;
                int gc = c0 + (e & 1);
                float val = acc[mt][j][e] + bias[gc];
                if (mode == 0) {
                    int bI = gr >> 11, nI = gr & (NN - 1);
                    int t3 = gc / 3;
                    int s3 = gc - 3 * t3;
                    int dd = t3 & 63;
                    int hh = gc / 192;
                    size_t idx = ((size_t)(bI * HH + hh) * NN + nI) * DD + dd;
                    if (s3 == 0)      split_st(g_qhi, g_qlo, idx, val * 8.0f);
                    else if (s3 == 1) split_st(g_khi, g_klo, idx, val);
                    else              split_st(g_vhi, g_vlo, idx, val);
                } else {
                    outp[(size_t)gr * EE + gc] = resid[(size_t)gr * EE + gc] + val;
                }
            }
        }
    }
}

// ---------------- flash attention via mma.sync -------------------------------
// 64q x 64k tiles, 8 warps (4m x 2n), warp tile 16x32. Q pre-scaled by 8.
#define ALD 72
#define SLD 68
// smem: 8 bf16 planes (Q,K,Vt,P hi/lo) + Sf32 + stats
#define PLN (64 * ALD * 2)              // 9216 B per bf16 plane
#define SF_OFF (8 * PLN)                // 73728
#define ST_OFF (SF_OFF + 64 * SLD * 4)  // +17408 = 91136
#define ATT_SMEM (ST_OFF + 3 * 64 * 4)  // 91904

__global__ __launch_bounds__(256, 2) void attn_mma() {
    extern __shared__ char smraw[];
    __nv_bfloat16* Qhi = (__nv_bfloat16*)smraw;
    __nv_bfloat16* Qlo = Qhi + 64 * ALD;
    __nv_bfloat16* Khi = Qlo + 64 * ALD;
    __nv_bfloat16* Klo = Khi + 64 * ALD;
    __nv_bfloat16* Vth = Klo + 64 * ALD;
    __nv_bfloat16* Vtl = Vth + 64 * ALD;
    __nv_bfloat16* Phi = Vtl + 64 * ALD;
    __nv_bfloat16* Plo = Phi + 64 * ALD;
    float* Sf   = (float*)(smraw + SF_OFF);
    float* mrow = (float*)(smraw + ST_OFF);
    float* lrow = mrow + 64;
    float* arow = lrow + 64;
    uint32_t sb = smem_u32(smraw);

    int b = blockIdx.z, h = blockIdx.y;
    int q0 = blockIdx.x * 64;
    int tid = threadIdx.x, wid = tid >> 5, lane = tid & 31;
    int wm = wid >> 1, wn = wid & 1;

    size_t hb = (size_t)(b * HH + h) * NN * DD;
    const __nv_bfloat16* qhig = g_qhi + hb + (size_t)q0 * DD;
    const __nv_bfloat16* qlog = g_qlo + hb + (size_t)q0 * DD;
    const __nv_bfloat16* khig = g_khi + hb;
    const __nv_bfloat16* klog = g_klo + hb;
    const __nv_bfloat16* vhig = g_vhi + hb;
    const __nv_bfloat16* vlog = g_vlo + hb;

    // load Q tile, init stats
    #pragma unroll
    for (int i = 0; i < 2; i++) {
        int idx = i * 256 + tid;
        int r = idx >> 3, c8 = (idx & 7) * 8;
        *(uint4*)(Qhi + r * ALD + c8) = *(const uint4*)(qhig + (size_t)r * DD + c8);
        *(uint4*)(Qlo + r * ALD + c8) = *(const uint4*)(qlog + (size_t)r * DD + c8);
    }
    if (tid < 64) { mrow[tid] = -1e30f; lrow[tid] = 0.f; }
    __syncthreads();

    // hoist Q fragments
    uint32_t qh[4][4], ql[4][4];
    #pragma unroll
    for (int ks = 0; ks < 4; ks++) {
        uint32_t ad = sb + ((wm * 16 + (lane & 15)) * ALD + ks * 16 + ((lane >> 4) * 8)) * 2;
        ldsm4(qh[ks], ad);
        ldsm4(ql[ks], ad + PLN);
    }

    float o[4][4];
    #pragma unroll
    for (int j = 0; j < 4; j++)
        #pragma unroll
        for (int e = 0; e < 4; e++) o[j][e] = 0.f;

    for (int kt = 0; kt < NN / 64; kt++) {
        __syncthreads();
        // load K planes + V transposed planes
        #pragma unroll
        for (int i = 0; i < 2; i++) {
            int idx = i * 256 + tid;
            int r = idx >> 3, c8 = (idx & 7) * 8;
            size_t gidx = (size_t)(kt * 64 + r) * DD + c8;
            *(uint4*)(Khi + r * ALD + c8) = *(const uint4*)(khig + gidx);
            *(uint4*)(Klo + r * ALD + c8) = *(const uint4*)(klog + gidx);
            uint4 vh = *(const uint4*)(vhig + gidx);
            uint4 vl = *(const uint4*)(vlog + gidx);
            const __nv_bfloat16* ph = reinterpret_cast<const __nv_bfloat16*>(&vh);
            const __nv_bfloat16* pl = reinterpret_cast<const __nv_bfloat16*>(&vl);
            #pragma unroll
            for (int jj = 0; jj < 8; jj++) {
                Vth[(c8 + jj) * ALD + r] = ph[jj];
                Vtl[(c8 + jj) * ALD + r] = pl[jj];
            }
        }
        __syncthreads();

        // S = Q K^T (3-term split)
        float s[4][4];
        #pragma unroll
        for (int j = 0; j < 4; j++)
            #pragma unroll
            for (int e = 0; e < 4; e++) s[j][e] = 0.f;
        #pragma unroll
        for (int ks = 0; ks < 4; ks++) {
            #pragma unroll
            for (int g = 0; g < 2; g++) {
                uint32_t r4h[4], r4l[4];
                uint32_t bd = sb + 2 * PLN +
                    ((wn * 32 + g * 16 + (lane & 15)) * ALD + ks * 16 + ((lane >> 4) * 8)) * 2;
                ldsm4(r4h, bd);
                ldsm4(r4l, bd + PLN);
                uint32_t bh0[2] = {r4h[0], r4h[2]}, bh1[2] = {r4h[1], r4h[3]};
                uint32_t bl0[2] = {r4l[0], r4l[2]}, bl1[2] = {r4l[1], r4l[3]};
                mma16816(s[g*2],   qh[ks], bh0);
                mma16816(s[g*2],   qh[ks], bl0);
                mma16816(s[g*2],   ql[ks], bh0);
                mma16816(s[g*2+1], qh[ks], bh1);
                mma16816(s[g*2+1], qh[ks], bl1);
                mma16816(s[g*2+1], ql[ks], bh1);
            }
        }
        // write S to smem
        {
            int rr = wm * 16 + (lane >> 2);
            #pragma unroll
            for (int j = 0; j < 4; j++) {
                int cc = wn * 32 + j * 8 + (lane & 3) * 2;
                Sf[rr * SLD + cc]       = s[j][0];
                Sf[rr * SLD + cc + 1]   = s[j][1];
                Sf[(rr+8) * SLD + cc]   = s[j][2];
                Sf[(rr+8) * SLD + cc+1] = s[j][3];
            }
        }
        __syncthreads();

        // softmax: 4 threads per row, 16 cols each; FFMA exp
        {
            int row = tid >> 2, q4 = tid & 3, c0 = q4 * 16;
            float sv[16];
            float mx = -1e30f;
            #pragma unroll
            for (int i = 0; i < 16; i++) {
                sv[i] = Sf[row * SLD + c0 + i];
                mx = fmaxf(mx, sv[i]);
            }
            mx = fmaxf(mx, __shfl_xor_sync(0xffffffffu, mx, 1));
            mx = fmaxf(mx, __shfl_xor_sync(0xffffffffu, mx, 2));
            float mold = mrow[row];
            float mnew = fmaxf(mold, mx);
            float sum = 0.f;
            #pragma unroll
            for (int i = 0; i < 16; i++) {
                float p = fexp(sv[i] - mnew);
                sum += p;
                __nv_bfloat16 phv = __float2bfloat16(p);
                Phi[row * ALD + c0 + i] = phv;
                Plo[row * ALD + c0 + i] = __float2bfloat16(p - __bfloat162float(phv));
            }
            sum += __shfl_xor_sync(0xffffffffu, sum, 1);
            sum += __shfl_xor_sync(0xffffffffu, sum, 2);
            if (q4 == 0) {
                float alpha = fexp(mold - mnew);
                mrow[row] = mnew;
                arow[row] = alpha;
                lrow[row] = lrow[row] * alpha + sum;
            }
        }
        __syncthreads();

        // rescale O, then O += P V (3-term split)
        float a_lo = arow[wm * 16 + (lane >> 2)];
        float a_hi = arow[wm * 16 + (lane >> 2) + 8];
        #pragma unroll
        for (int j = 0; j < 4; j++) {
            o[j][0] *= a_lo; o[j][1] *= a_lo;
            o[j][2] *= a_hi; o[j][3] *= a_hi;
        }
        #pragma unroll
        for (int ks = 0; ks < 4; ks++) {
            uint32_t aph[4], apl[4];
            uint32_t pad = sb + 6 * PLN +
                ((wm * 16 + (lane & 15)) * ALD + ks * 16 + ((lane >> 4) * 8)) * 2;
            ldsm4(aph, pad);
            ldsm4(apl, pad + PLN);
            #pragma unroll
            for (int g = 0; g < 2; g++) {
                uint32_t r4h[4], r4l[4];
                uint32_t vd = sb + 4 * PLN +
                    ((wn * 32 + g * 16 + (lane & 15)) * ALD + ks * 16 + ((lane >> 4) * 8)) * 2;
                ldsm4(r4h, vd);
                ldsm4(r4l, vd + PLN);
                uint32_t bh0[2] = {r4h[0], r4h[2]}, bh1[2] = {r4h[1], r4h[3]};
                uint32_t bl0[2] = {r4l[0], r4l[2]}, bl1[2] = {r4l[1], r4l[3]};
                mma16816(o[g*2],   aph, bh0);
                mma16816(o[g*2],   aph, bl0);
                mma16816(o[g*2],   apl, bh0);
                mma16816(o[g*2+1], aph, bh1);
                mma16816(o[g*2+1], aph, bl1);
                mma16816(o[g*2+1], apl, bh1);
            }
        }
    }

    // epilogue: out = O / l, split to hi/lo planes at [b][n][h*64+d]
    float li_lo = 1.0f / lrow[wm * 16 + (lane >> 2)];
    float li_hi = 1.0f / lrow[wm * 16 + (lane >> 2) + 8];
    int rr = q0 + wm * 16 + (lane >> 2);
    #pragma unroll
    for (int j = 0; j < 4; j++) {
        int dd = wn * 32 + j * 8 + (lane & 3) * 2;
        size_t o0 = ((size_t)b * NN + rr) * EE + h * DD + dd;
        split_st(g_att_hi, g_att_lo, o0,     o[j][0] * li_lo);
        split_st(g_att_hi, g_att_lo, o0 + 1, o[j][1] * li_lo);
        size_t o8 = o0 + (size_t)8 * EE;
        split_st(g_att_hi, g_att_lo, o8,     o[j][2] * li_hi);
        split_st(g_att_hi, g_att_lo, o8 + 1, o[j][3] * li_hi);
    }
}

// ---------------- launch -----------------------------------------------------
extern "C" void kernel_launch(void* const* d_in, const int* in_sizes, int n_in,
                              void* d_out, int out_size) {
    const float* in[14];
    for (int i = 0; i < 14; i++) in[i] = (const float*)d_in[i];
    float* out = (float*)d_out;

    cudaFuncSetAttribute(gemm_mma,
                         cudaFuncAttributeMaxDynamicSharedMemorySize, GEMM_SMEM);
    cudaFuncSetAttribute(attn_mma,
                         cudaFuncAttributeMaxDynamicSharedMemorySize, ATT_SMEM);

    for (int m = 0; m < 2; m++) {
        const float* x    = in[m];
        const float* ln_g = in[2 + 6 * m];
        const float* ln_b = in[3 + 6 * m];
        const float* wq   = in[4 + 6 * m];
        const float* bq   = in[5 + 6 * m];
        const float* wp   = in[6 + 6 * m];
        const float* bp   = in[7 + 6 * m];
        float* outm = out + (size_t)m * MM * EE;

        ln_kernel<<<MM, 256>>>(x, ln_g, ln_b);
        split_kernel<<<(E3 * EE + 255) / 256, 256>>>(wq, E3 * EE);
        gemm_mma<<<dim3(E3 / 128, MM / 128), 256, GEMM_SMEM>>>(bq, nullptr, nullptr, 0);
        attn_mma<<<dim3(NN / 64, HH, BB), 256, ATT_SMEM>>>();
        split_kernel<<<(EE * EE + 255) / 256, 256>>>(wp, EE * EE);
        gemm_mma<<<dim3(EE / 128, MM / 128), 256, GEMM_SMEM>>>(bp, x, outm, 1);
    }
}

// round 7
// speedup vs baseline: 2.5289x; 1.5737x over previous
#include <cuda_runtime.h>
#include <cuda_bf16.h>
#include <cstdint>

// Problem constants
#define BB 2
#define NN 2048
#define EE 768
#define HH 12
#define DD 64
#define E3 (3*EE)
#define MM (BB*NN)   // 4096 rows

// 8 * log2(e): folds the softmax exp->exp2 conversion into the Q scale
#define QSCALE 11.541560327111707f

// ------------------------------ helpers ------------------------------------
__device__ __forceinline__ uint32_t smem_u32(const void* p) {
    uint32_t a;
    asm("{ .reg .u64 t; cvta.to.shared.u64 t, %1; cvt.u32.u64 %0, t; }"
        : "=r"(a) : "l"(p));
    return a;
}
__device__ __forceinline__ void ldsm4(uint32_t* r, uint32_t addr) {
    asm volatile("ldmatrix.sync.aligned.m8n8.x4.shared.b16 {%0,%1,%2,%3}, [%4];"
        : "=r"(r[0]), "=r"(r[1]), "=r"(r[2]), "=r"(r[3]) : "r"(addr));
}
__device__ __forceinline__ void ldsm4t(uint32_t* r, uint32_t addr) {
    asm volatile("ldmatrix.sync.aligned.m8n8.x4.trans.shared.b16 {%0,%1,%2,%3}, [%4];"
        : "=r"(r[0]), "=r"(r[1]), "=r"(r[2]), "=r"(r[3]) : "r"(addr));
}
__device__ __forceinline__ void mma16816(float* c, const uint32_t* a, const uint32_t* b) {
    asm volatile("mma.sync.aligned.m16n8k16.row.col.f32.bf16.bf16.f32 "
        "{%0,%1,%2,%3}, {%4,%5,%6,%7}, {%8,%9}, {%0,%1,%2,%3};"
        : "+f"(c[0]), "+f"(c[1]), "+f"(c[2]), "+f"(c[3])
        : "r"(a[0]), "r"(a[1]), "r"(a[2]), "r"(a[3]), "r"(b[0]), "r"(b[1]));
}
__device__ __forceinline__ float ex2f(float x) {
    float y; asm("ex2.approx.f32 %0, %1;" : "=f"(y) : "f"(x)); return y;
}
__device__ __forceinline__ uint32_t cvt2(float hi, float lo) {
    uint32_t r; asm("cvt.rn.bf16x2.f32 %0, %1, %2;" : "=r"(r) : "f"(hi), "f"(lo));
    return r;
}
__device__ __forceinline__ void cpa16(uint32_t dst, const void* src) {
    asm volatile("cp.async.cg.shared.global [%0], [%1], 16;" :: "r"(dst), "l"(src));
}
#define CP_COMMIT() asm volatile("cp.async.commit_group;" ::: "memory")
#define CP_WAIT(n)  asm volatile("cp.async.wait_group %0;" :: "n"(n) : "memory")

__device__ __forceinline__ void split_st(__nv_bfloat16* hi, __nv_bfloat16* lo,
                                         size_t idx, float v) {
    __nv_bfloat16 h = __float2bfloat16(v);
    hi[idx] = h;
    lo[idx] = __float2bfloat16(v - __bfloat162float(h));
}

// ---------------- scratch (device globals; DEVICE-SIDE refs only!) ---------
__device__ __align__(256) __nv_bfloat16 g_xn_hi[MM*EE],  g_xn_lo[MM*EE];
__device__ __align__(256) __nv_bfloat16 g_att_hi[MM*EE], g_att_lo[MM*EE];
__device__ __align__(256) __nv_bfloat16 g_w_hi[E3*EE],   g_w_lo[E3*EE];
__device__ __align__(256) __nv_bfloat16 g_qhi[BB*HH*NN*DD], g_qlo[BB*HH*NN*DD];
__device__ __align__(256) __nv_bfloat16 g_khi[BB*HH*NN*DD], g_klo[BB*HH*NN*DD];
__device__ __align__(256) __nv_bfloat16 g_vhi[BB*HH*NN*DD], g_vlo[BB*HH*NN*DD];

// ---------------- LayerNorm + hi/lo split ----------------------------------
__global__ __launch_bounds__(256) void ln_kernel(const float* __restrict__ x,
                                                 const float* __restrict__ g,
                                                 const float* __restrict__ bta) {
    int row = blockIdx.x;
    const float* xr = x + (size_t)row * EE;
    int t = threadIdx.x;
    float v0 = xr[t], v1 = xr[t + 256], v2 = xr[t + 512];
    float s  = v0 + v1 + v2;
    float sq = v0*v0 + v1*v1 + v2*v2;
    __shared__ float rs[8], rq[8];
    #pragma unroll
    for (int o = 16; o; o >>= 1) {
        s  += __shfl_xor_sync(0xffffffffu, s,  o);
        sq += __shfl_xor_sync(0xffffffffu, sq, o);
    }
    if ((t & 31) == 0) { rs[t >> 5] = s; rq[t >> 5] = sq; }
    __syncthreads();
    float S = 0.f, Q = 0.f;
    #pragma unroll
    for (int i = 0; i < 8; i++) { S += rs[i]; Q += rq[i]; }
    float mu  = S * (1.0f / EE);
    float var = Q * (1.0f / EE) - mu * mu;
    float inv = rsqrtf(var + 1e-5f);
    #pragma unroll
    for (int p = 0; p < 3; p++) {
        int c = t + p * 256;
        float v = (p == 0 ? v0 : p == 1 ? v1 : v2);
        float y = (v - mu) * inv * g[c] + bta[c];
        split_st(g_xn_hi, g_xn_lo, (size_t)row * EE + c, y);
    }
}

__global__ __launch_bounds__(256) void split_kernel(const float* __restrict__ src, int n) {
    int i = blockIdx.x * 256 + threadIdx.x;
    if (i < n) split_st(g_w_hi, g_w_lo, i, src[i]);
}

// ---------------- split-bf16 GEMM via mma.sync (unchanged from R6) ----------
#define GLD 72
#define GEMM_SMEM (4 * 128 * GLD * 2)   // 73728 B

__global__ __launch_bounds__(256, 2) void gemm_mma(
        const float* __restrict__ bias,
        const float* __restrict__ resid, float* __restrict__ outp, int mode) {
    extern __shared__ char smraw[];
    __nv_bfloat16* sAh = (__nv_bfloat16*)smraw;
    __nv_bfloat16* sAl = sAh + 128 * GLD;
    __nv_bfloat16* sBh = sAl + 128 * GLD;
    __nv_bfloat16* sBl = sBh + 128 * GLD;
    uint32_t sb = smem_u32(smraw);
    const uint32_t PLANE = 128 * GLD * 2;

    const __nv_bfloat16* __restrict__ Ahi = (mode == 0) ? g_xn_hi : g_att_hi;
    const __nv_bfloat16* __restrict__ Alo = (mode == 0) ? g_xn_lo : g_att_lo;

    int tid = threadIdx.x;
    int wid = tid >> 5, lane = tid & 31;
    int wm = wid >> 1, wn = wid & 1;
    int m0 = blockIdx.y * 128, n0 = blockIdx.x * 128;

    float acc[2][8][4];
    #pragma unroll
    for (int a = 0; a < 2; a++)
        #pragma unroll
        for (int b = 0; b < 8; b++)
            #pragma unroll
            for (int c = 0; c < 4; c++) acc[a][b][c] = 0.f;

    for (int k0 = 0; k0 < EE; k0 += 64) {
        __syncthreads();
        #pragma unroll
        for (int i = 0; i < 4; i++) {
            int idx = i * 256 + tid;
            int r = idx >> 3, c8 = (idx & 7) * 8;
            *(uint4*)(sAh + r * GLD + c8) =
                *(const uint4*)(Ahi + (size_t)(m0 + r) * EE + k0 + c8);
            *(uint4*)(sAl + r * GLD + c8) =
                *(const uint4*)(Alo + (size_t)(m0 + r) * EE + k0 + c8);
            *(uint4*)(sBh + r * GLD + c8) =
                *(const uint4*)(g_w_hi + (size_t)(n0 + r) * EE + k0 + c8);
            *(uint4*)(sBl + r * GLD + c8) =
                *(const uint4*)(g_w_lo + (size_t)(n0 + r) * EE + k0 + c8);
        }
        __syncthreads();
        #pragma unroll
        for (int ks = 0; ks < 4; ks++) {
            uint32_t ah[2][4], al[2][4];
            #pragma unroll
            for (int mt = 0; mt < 2; mt++) {
                uint32_t ad = sb +
                    ((wm * 32 + mt * 16 + (lane & 15)) * GLD + ks * 16 + ((lane >> 4) * 8)) * 2;
                ldsm4(ah[mt], ad);
                ldsm4(al[mt], ad + PLANE);
            }
            #pragma unroll
            for (int g = 0; g < 4; g++) {
                uint32_t r4h[4], r4l[4];
                uint32_t bd = sb + 2 * PLANE +
                    ((wn * 64 + g * 16 + (lane & 15)) * GLD + ks * 16 + ((lane >> 4) * 8)) * 2;
                ldsm4(r4h, bd);
                ldsm4(r4l, bd + PLANE);
                uint32_t bh0[2] = {r4h[0], r4h[2]}, bh1[2] = {r4h[1], r4h[3]};
                uint32_t bl0[2] = {r4l[0], r4l[2]}, bl1[2] = {r4l[1], r4l[3]};
                #pragma unroll
                for (int mt = 0; mt < 2; mt++) {
                    mma16816(acc[mt][g*2],   ah[mt], bh0);
                    mma16816(acc[mt][g*2],   ah[mt], bl0);
                    mma16816(acc[mt][g*2],   al[mt], bh0);
                    mma16816(acc[mt][g*2+1], ah[mt], bh1);
                    mma16816(acc[mt][g*2+1], ah[mt], bl1);
                    mma16816(acc[mt][g*2+1], al[mt], bh1);
                }
            }
        }
    }

    #pragma unroll
    for (int mt = 0; mt < 2; mt++) {
        int r0 = m0 + wm * 32 + mt * 16 + (lane >> 2);
        #pragma unroll
        for (int j = 0; j < 8; j++) {
            int c0 = n0 + wn * 64 + j * 8 + (lane & 3) * 2;
            #pragma unroll
            for (int e = 0; e < 4; e++) {
                int gr = r0 + (e >> 1) * 8;
                int gc = c0 + (e & 1);
                float val = acc[mt][j][e] + bias[gc];
                if (mode == 0) {
                    int bI = gr >> 11, nI = gr & (NN - 1);
                    int t3 = gc / 3;
                    int s3 = gc - 3 * t3;
                    int dd = t3 & 63;
                    int hh = gc / 192;
                    size_t idx = ((size_t)(bI * HH + hh) * NN + nI) * DD + dd;
                    if (s3 == 0)      split_st(g_qhi, g_qlo, idx, val * QSCALE);
                    else if (s3 == 1) split_st(g_khi, g_klo, idx, val);
                    else              split_st(g_vhi, g_vlo, idx, val);
                } else {
                    outp[(size_t)gr * EE + gc] = resid[(size_t)gr * EE + gc] + val;
                }
            }
        }
    }
}

// ---------------- FA2-style flash attention ---------------------------------
// 128q tile per CTA, 8 warps, warp = 16q x all 64k. P stays in registers
// (S accumulator fragments == PV A-operand fragments). V via ldmatrix.trans.
// K/V double-buffered with cp.async. exp via MUFU ex2 (log2e folded into Q).
#define ALD 72
#define QPLN (128 * ALD * 2)        // 18432 per Q plane
#define KPLN (64 * ALD * 2)         // 9216 per K/V plane
#define STG  (4 * KPLN)             // 36864 per stage (Khi,Klo,Vhi,Vlo)
#define ATT_SMEM (2*QPLN + 2*STG)   // 110592

__device__ __forceinline__ void load_kv_stage(
        uint32_t stg, int kt, int tid,
        const __nv_bfloat16* khig, const __nv_bfloat16* klog,
        const __nv_bfloat16* vhig, const __nv_bfloat16* vlog) {
    const __nv_bfloat16* srcs[4] = {khig, klog, vhig, vlog};
    #pragma unroll
    for (int p = 0; p < 4; p++) {
        #pragma unroll
        for (int i = 0; i < 2; i++) {
            int idx = i * 256 + tid;
            int r = idx >> 3, c8 = (idx & 7) * 8;
            cpa16(stg + (uint32_t)p * KPLN + (r * ALD + c8) * 2,
                  srcs[p] + (size_t)(kt * 64 + r) * DD + c8);
        }
    }
}

__global__ __launch_bounds__(256, 2) void attn_mma() {
    extern __shared__ char smraw[];
    __nv_bfloat16* sQh = (__nv_bfloat16*)smraw;
    __nv_bfloat16* sQl = sQh + 128 * ALD;
    uint32_t sb = smem_u32(smraw);

    int b = blockIdx.z, h = blockIdx.y;
    int q0 = blockIdx.x * 128;
    int tid = threadIdx.x, wid = tid >> 5, lane = tid & 31;
    int rb = wid * 16;                 // warp's q-row base within tile
    int tg = lane >> 2, tig = lane & 3;

    size_t hb = (size_t)(b * HH + h) * NN * DD;
    const __nv_bfloat16* khig = g_khi + hb;
    const __nv_bfloat16* klog = g_klo + hb;
    const __nv_bfloat16* vhig = g_vhi + hb;
    const __nv_bfloat16* vlog = g_vlo + hb;

    // stage Q (once)
    #pragma unroll
    for (int i = 0; i < 4; i++) {
        int idx = i * 256 + tid;            // 0..1023 -> 128 rows x 8 uint4
        int r = idx >> 3, c8 = (idx & 7) * 8;
        size_t gq = hb + (size_t)(q0 + r) * DD + c8;
        *(uint4*)(sQh + r * ALD + c8) = *(const uint4*)(g_qhi + gq);
        *(uint4*)(sQl + r * ALD + c8) = *(const uint4*)(g_qlo + gq);
    }
    // prefetch stage 0
    load_kv_stage(sb + 2 * QPLN, 0, tid, khig, klog, vhig, vlog);
    CP_COMMIT();
    __syncthreads();

    // hoist Q-hi fragments
    uint32_t qh[4][4];
    #pragma unroll
    for (int ks = 0; ks < 4; ks++)
        ldsm4(qh[ks], sb + ((rb + (lane & 15)) * ALD + ks * 16 + ((lane >> 4) * 8)) * 2);

    float o[8][4];
    #pragma unroll
    for (int g = 0; g < 8; g++)
        #pragma unroll
        for (int e = 0; e < 4; e++) o[g][e] = 0.f;
    float m0 = -1e30f, m1 = -1e30f, l0 = 0.f, l1 = 0.f;

    const int NT = NN / 64;
    for (int kt = 0; kt < NT; kt++) {
        uint32_t sk = sb + 2 * QPLN + (uint32_t)(kt & 1) * STG;
        if (kt + 1 < NT) {
            load_kv_stage(sb + 2 * QPLN + (uint32_t)((kt + 1) & 1) * STG,
                          kt + 1, tid, khig, klog, vhig, vlog);
            CP_COMMIT();
            CP_WAIT(1);
        } else {
            CP_WAIT(0);
        }
        __syncthreads();

        // ---- S = Q K^T (16 x 64, 3-term split) ----
        float s[8][4];
        #pragma unroll
        for (int g = 0; g < 8; g++)
            #pragma unroll
            for (int e = 0; e < 4; e++) s[g][e] = 0.f;
        #pragma unroll
        for (int ks = 0; ks < 4; ks++) {
            uint32_t ql4[4];
            ldsm4(ql4, sb + QPLN + ((rb + (lane & 15)) * ALD + ks * 16 + ((lane >> 4) * 8)) * 2);
            #pragma unroll
            for (int nb = 0; nb < 4; nb++) {
                uint32_t r4h[4], r4l[4];
                uint32_t bd = sk + ((nb * 16 + (lane & 15)) * ALD + ks * 16 + ((lane >> 4) * 8)) * 2;
                ldsm4(r4h, bd);
                ldsm4(r4l, bd + KPLN);
                uint32_t bh0[2] = {r4h[0], r4h[2]}, bh1[2] = {r4h[1], r4h[3]};
                uint32_t bl0[2] = {r4l[0], r4l[2]}, bl1[2] = {r4l[1], r4l[3]};
                mma16816(s[nb*2],   qh[ks], bh0);
                mma16816(s[nb*2],   qh[ks], bl0);
                mma16816(s[nb*2],   ql4,    bh0);
                mma16816(s[nb*2+1], qh[ks], bh1);
                mma16816(s[nb*2+1], qh[ks], bl1);
                mma16816(s[nb*2+1], ql4,    bh1);
            }
        }

        // ---- softmax in registers (rows tg and tg+8; scores already *log2e) --
        float mx0 = -1e30f, mx1 = -1e30f;
        #pragma unroll
        for (int g = 0; g < 8; g++) {
            mx0 = fmaxf(mx0, fmaxf(s[g][0], s[g][1]));
            mx1 = fmaxf(mx1, fmaxf(s[g][2], s[g][3]));
        }
        mx0 = fmaxf(mx0, __shfl_xor_sync(0xffffffffu, mx0, 1));
        mx0 = fmaxf(mx0, __shfl_xor_sync(0xffffffffu, mx0, 2));
        mx1 = fmaxf(mx1, __shfl_xor_sync(0xffffffffu, mx1, 1));
        mx1 = fmaxf(mx1, __shfl_xor_sync(0xffffffffu, mx1, 2));
        float nm0 = fmaxf(m0, mx0), nm1 = fmaxf(m1, mx1);
        float a0 = ex2f(m0 - nm0), a1 = ex2f(m1 - nm1);
        m0 = nm0; m1 = nm1;

        uint32_t ph01[8], ph23[8], pl01[8], pl23[8];
        float sum0 = 0.f, sum1 = 0.f;
        #pragma unroll
        for (int g = 0; g < 8; g++) {
            float e0 = ex2f(s[g][0] - nm0), e1 = ex2f(s[g][1] - nm0);
            float e2 = ex2f(s[g][2] - nm1), e3 = ex2f(s[g][3] - nm1);
            sum0 += e0 + e1;  sum1 += e2 + e3;
            uint32_t h01 = cvt2(e1, e0);
            uint32_t h23 = cvt2(e3, e2);
            float r0 = e0 - __int_as_float(h01 << 16);
            float r1 = e1 - __int_as_float(h01 & 0xffff0000u);
            float r2 = e2 - __int_as_float(h23 << 16);
            float r3 = e3 - __int_as_float(h23 & 0xffff0000u);
            ph01[g] = h01; ph23[g] = h23;
            pl01[g] = cvt2(r1, r0); pl23[g] = cvt2(r3, r2);
        }
        sum0 += __shfl_xor_sync(0xffffffffu, sum0, 1);
        sum0 += __shfl_xor_sync(0xffffffffu, sum0, 2);
        sum1 += __shfl_xor_sync(0xffffffffu, sum1, 1);
        sum1 += __shfl_xor_sync(0xffffffffu, sum1, 2);
        l0 = l0 * a0 + sum0;
        l1 = l1 * a1 + sum1;
        #pragma unroll
        for (int g = 0; g < 8; g++) {
            o[g][0] *= a0; o[g][1] *= a0;
            o[g][2] *= a1; o[g][3] *= a1;
        }

        // ---- O += P V (P in registers; V via ldmatrix.trans; 3-term) ----
        uint32_t sv = sk + 2 * KPLN;
        #pragma unroll
        for (int kg = 0; kg < 4; kg++) {
            uint32_t aph[4] = {ph01[2*kg], ph23[2*kg], ph01[2*kg+1], ph23[2*kg+1]};
            uint32_t apl[4] = {pl01[2*kg], pl23[2*kg], pl01[2*kg+1], pl23[2*kg+1]};
            #pragma unroll
            for (int db = 0; db < 4; db++) {
                uint32_t r4h[4], r4l[4];
                uint32_t vd = sv + ((kg * 16 + (lane & 15)) * ALD + db * 16 + ((lane >> 4) * 8)) * 2;
                ldsm4t(r4h, vd);
                ldsm4t(r4l, vd + KPLN);
                uint32_t bh0[2] = {r4h[0], r4h[1]}, bh1[2] = {r4h[2], r4h[3]};
                uint32_t bl0[2] = {r4l[0], r4l[1]}, bl1[2] = {r4l[2], r4l[3]};
                mma16816(o[db*2],   aph, bh0);
                mma16816(o[db*2],   aph, bl0);
                mma16816(o[db*2],   apl, bh0);
                mma16816(o[db*2+1], aph, bh1);
                mma16816(o[db*2+1], aph, bl1);
                mma16816(o[db*2+1], apl, bh1);
            }
        }
        __syncthreads();   // all reads of stage (kt&1) done before next overwrite
    }

    // ---- epilogue: att = O / l, split-store to g_att planes ----
    float inv0 = 1.0f / l0, inv1 = 1.0f / l1;
    int rr0 = q0 + rb + tg;
    #pragma unroll
    for (int g = 0; g < 8; g++) {
        int dd = g * 8 + tig * 2;
        size_t o0 = ((size_t)b * NN + rr0) * EE + h * DD + dd;
        split_st(g_att_hi, g_att_lo, o0,     o[g][0] * inv0);
        split_st(g_att_hi, g_att_lo, o0 + 1, o[g][1] * inv0);
        size_t o8 = o0 + (size_t)8 * EE;
        split_st(g_att_hi, g_att_lo, o8,     o[g][2] * inv1);
        split_st(g_att_hi, g_att_lo, o8 + 1, o[g][3] * inv1);
    }
}

// ---------------- launch -----------------------------------------------------
extern "C" void kernel_launch(void* const* d_in, const int* in_sizes, int n_in,
                              void* d_out, int out_size) {
    const float* in[14];
    for (int i = 0; i < 14; i++) in[i] = (const float*)d_in[i];
    float* out = (float*)d_out;

    cudaFuncSetAttribute(gemm_mma,
                         cudaFuncAttributeMaxDynamicSharedMemorySize, GEMM_SMEM);
    cudaFuncSetAttribute(attn_mma,
                         cudaFuncAttributeMaxDynamicSharedMemorySize, ATT_SMEM);

    for (int m = 0; m < 2; m++) {
        const float* x    = in[m];
        const float* ln_g = in[2 + 6 * m];
        const float* ln_b = in[3 + 6 * m];
        const float* wq   = in[4 + 6 * m];
        const float* bq   = in[5 + 6 * m];
        const float* wp   = in[6 + 6 * m];
        const float* bp   = in[7 + 6 * m];
        float* outm = out + (size_t)m * MM * EE;

        ln_kernel<<<MM, 256>>>(x, ln_g, ln_b);
        split_kernel<<<(E3 * EE + 255) / 256, 256>>>(wq, E3 * EE);
        gemm_mma<<<dim3(E3 / 128, MM / 128), 256, GEMM_SMEM>>>(bq, nullptr, nullptr, 0);
        attn_mma<<<dim3(NN / 128, HH, BB), 256, ATT_SMEM>>>();
        split_kernel<<<(EE * EE + 255) / 256, 256>>>(wp, EE * EE);
        gemm_mma<<<dim3(EE / 128, MM / 128), 256, GEMM_SMEM>>>(bp, x, outm, 1);
    }
}